// round 14
// baseline (speedup 1.0000x reference)
#include <cuda_runtime.h>
#include <cuda_bf16.h>
#include <cstdint>

#define BB 8
#define CC 2048
#define FIN 128
#define FF 64
#define NROWS (BB*CC)
#define LOG2E 1.4426950408889634f

// Scratch (__device__ globals: allocation-free rule)
// g_WhP: paired layout, per 64-row group (= global row>>6), 4096 floats:
//   offset = grp64*4096 + kt*128 + col*2 + h,  kt=(q>>3)*4+(q&3), h=(q>>2)&1.
__device__ float g_WhP[(size_t)NROWS * FF];
__device__ float g_s1[NROWS];                 // s1 * log2e
__device__ float g_s2[NROWS];                 // s2 * log2e
__device__ float g_part[512][64][72];         // per (tile,half): unnorm acc + l at col 64
__device__ float g_partm[512][64];            // per (tile,half): running row max (exp2 dom)
__device__ int   g_done[256];                 // per-tile arrival counter (reset each use)

__device__ __forceinline__ float f2tf32f(float x) {
    uint32_t r;
    asm("cvt.rna.tf32.f32 %0, %1;" : "=r"(r) : "f"(x));
    return __uint_as_float(r);
}
__device__ __forceinline__ float ex2f(float x) {
    float r;
    asm("ex2.approx.f32 %0, %1;" : "=f"(r) : "f"(x));
    return r;
}
__device__ __forceinline__ void mma_tf32(float* c,
                                         uint32_t a0, uint32_t a1, uint32_t a2, uint32_t a3,
                                         uint32_t b0, uint32_t b1) {
    asm volatile(
        "mma.sync.aligned.m16n8k8.row.col.f32.tf32.tf32.f32 "
        "{%0,%1,%2,%3}, {%4,%5,%6,%7}, {%8,%9}, {%0,%1,%2,%3};"
        : "+f"(c[0]), "+f"(c[1]), "+f"(c[2]), "+f"(c[3])
        : "r"(a0), "r"(a1), "r"(a2), "r"(a3), "r"(b0), "r"(b1));
}

// ---------------------------------------------------------------------------
// Kernel 1 v2: Wh = H @ W, 32 rows/block (grid 512), + s1,s2 (x log2e).
// Per-thread rows = two (q, q+4) pairs -> paired g_WhP float4 stays in-thread.
// HsT stride 46: conflict-light transpose stores, broadcast reads.
// ---------------------------------------------------------------------------
__global__ __launch_bounds__(256) void k_wh(const float* __restrict__ H,
                                            const float* __restrict__ W,
                                            const float* __restrict__ a)
{
    __shared__ float HsT[32][46];     // [k][perm(row)], perm(r)=r+(r>>3)*4 (max 43)
    __shared__ float Ws[32][68];      // [k][col]

    int t  = threadIdx.x;
    int tx = t & 31;                  // cols 2tx, 2tx+1
    int ty = t >> 5;                  // 0..7
    int m  = ty >> 1;                 // 8-row block 0..3
    int s0 = (ty & 1) * 2;            // rows: m*8+s0, +1, +4, +5
    int r0 = blockIdx.x * 32;

    float acc[4][2] = {};             // [0]=q0 [1]=q0+1 [2]=q0+4 [3]=q0+5

    for (int kc = 0; kc < 4; kc++) {
        __syncthreads();
        {   // H tile transposed: 32 rows x 32 k (1 float4/thread)
            int r = t >> 3, c4 = t & 7;
            float4 v = *(const float4*)(H + (size_t)(r0 + r) * FIN + kc * 32 + c4 * 4);
            int pr = r + ((r >> 3) << 2);
            HsT[c4 * 4 + 0][pr] = v.x;
            HsT[c4 * 4 + 1][pr] = v.y;
            HsT[c4 * 4 + 2][pr] = v.z;
            HsT[c4 * 4 + 3][pr] = v.w;
        }
        {   // W chunk
#pragma unroll
            for (int p = 0; p < 2; p++) {
                int idx = t + p * 256;
                int row = idx >> 4, c4 = idx & 15;
                *(float4*)&Ws[row][c4 * 4] = *(const float4*)(W + (size_t)(kc * 32 + row) * FF + c4 * 4);
            }
        }
        __syncthreads();

#pragma unroll
        for (int k = 0; k < 32; k++) {
            float2 w   = *(const float2*)&Ws[k][tx * 2];
            float2 hlo = *(const float2*)&HsT[k][m * 12 + s0];       // q0, q0+1
            float2 hhi = *(const float2*)&HsT[k][m * 12 + s0 + 4];   // q0+4, q0+5
            acc[0][0] = fmaf(hlo.x, w.x, acc[0][0]); acc[0][1] = fmaf(hlo.x, w.y, acc[0][1]);
            acc[1][0] = fmaf(hlo.y, w.x, acc[1][0]); acc[1][1] = fmaf(hlo.y, w.y, acc[1][1]);
            acc[2][0] = fmaf(hhi.x, w.x, acc[2][0]); acc[2][1] = fmaf(hhi.x, w.y, acc[2][1]);
            acc[3][0] = fmaf(hhi.y, w.x, acc[3][0]); acc[3][1] = fmaf(hhi.y, w.y, acc[3][1]);
        }
    }

    // epilogue: s1/s2 per row (warp reduce over tx)
    float a10 = a[tx * 2], a11 = a[tx * 2 + 1];
    float a20 = a[FF + tx * 2], a21 = a[FF + tx * 2 + 1];
    int qrow[4] = { m * 8 + s0, m * 8 + s0 + 1, m * 8 + s0 + 4, m * 8 + s0 + 5 };

#pragma unroll
    for (int rr = 0; rr < 4; rr++) {
        int r = r0 + qrow[rr];
        float p1 = acc[rr][0] * a10 + acc[rr][1] * a11;
        float p2 = acc[rr][0] * a20 + acc[rr][1] * a21;
#pragma unroll
        for (int off = 16; off; off >>= 1) {
            p1 += __shfl_xor_sync(0xffffffffu, p1, off);
            p2 += __shfl_xor_sync(0xffffffffu, p2, off);
        }
        if (tx == 0) { g_s1[r] = p1 * LOG2E; g_s2[r] = p2 * LOG2E; }
    }

    // paired g_WhP writes: kt = m*4+s0 (+1), rows (q, q+4) packed in one float4
    float* dst = g_WhP + (size_t)(blockIdx.x >> 1) * 4096
               + (size_t)((blockIdx.x & 1) * 16) * 128;
    {
        int kt = m * 4 + s0;
        float4 v0, v1;
        v0.x = f2tf32f(acc[0][0]); v0.y = f2tf32f(acc[2][0]);
        v0.z = f2tf32f(acc[0][1]); v0.w = f2tf32f(acc[2][1]);
        v1.x = f2tf32f(acc[1][0]); v1.y = f2tf32f(acc[3][0]);
        v1.z = f2tf32f(acc[1][1]); v1.w = f2tf32f(acc[3][1]);
        *(float4*)(dst + kt * 128 + tx * 4)       = v0;
        *(float4*)(dst + (kt + 1) * 128 + tx * 4) = v1;
    }
}

// ---------------------------------------------------------------------------
// k_out: SINGLE-PASS online-softmax @ Wh (R12 mainloop, unchanged) + fused
// combine epilogue: last-arriving half of each tile merges both halves and
// writes the final output (fence + per-tile atomic counter, reset for graphs).
// ---------------------------------------------------------------------------
// dynamic smem (bytes):
//   maskC : uint32[64][8]       @ 0      (2048)   (reused as flag word at end)
//   s2S   : float [1024]        @ 2048   (4096)
//   s2pair: float2[512]         @ 6144   (4096)
//   whsP  : float [2][4352]     @ 10240  (34816)  (aliased as accS at end)
//   s1s   : float [64]          @ 45056  (256)
//   msS   : float [64]          @ 45312  (256)
//   fsS   : float [64]          @ 45568  (256)
#define KOUT_SMEM 45824

__global__ __launch_bounds__(256, 4) void k_out(const int* __restrict__ A,
                                                float* __restrict__ out)
{
    extern __shared__ char smemraw[];
    uint32_t (*maskC)[8] = (uint32_t(*)[8])smemraw;
    float*  s2S    = (float*)(smemraw + 2048);
    float2* s2pair = (float2*)(smemraw + 6144);
    float*  whsP   = (float*)(smemraw + 10240);
    float*  s1s    = (float*)(smemraw + 45056);
    float*  msS    = (float*)(smemraw + 45312);
    float*  fsS    = (float*)(smemraw + 45568);

    int t = threadIdx.x;
    int lane = t & 31;
    int warp = t >> 5;
    int grp  = t >> 7;
    int lt   = t & 127;
    int wg   = warp & 3;
    int g = lane >> 2, tg = lane & 3;
    int m0 = wg * 16;

    int bid  = blockIdx.x;
    int half = bid & 1;
    int tile = bid >> 1;
    int b  = tile >> 5;
    int i0 = (tile & 31) << 6;
    int J0 = half << 10;
    const int* Ab = A + (size_t)b * CC * CC;

    if (t < 64) {
        s1s[t] = g_s1[b * CC + i0 + t];
        msS[t] = -3.0e38f;
    }
    for (int q = t; q < 1024; q += 256) s2S[q] = g_s2[b * CC + J0 + q];
    __syncthreads();
#pragma unroll
    for (int p = 0; p < 2; p++) {
        int idx = t + p * 256;
        int gj = idx >> 2, tgq = idx & 3;
        s2pair[idx] = make_float2(s2S[gj * 8 + tgq], s2S[gj * 8 + tgq + 4]);
    }

    float4 acc[8];
#pragma unroll
    for (int nf = 0; nf < 8; nf++) acc[nf] = make_float4(0.f, 0.f, 0.f, 0.f);
    float lA = 0.f, lB = 0.f;

    int gbase = (b * 32) + (J0 >> 6);
    int myrowA = m0 + g, myrowB = m0 + g + 8;

    uint32_t whs_sb = (uint32_t)__cvta_generic_to_shared(whsP);

    for (int o = 0; o < 8; o++) {
        __syncthreads();                     // protect maskC/whsP/fsS reuse

        // -- stage Wh tile o via cp.async (drains during compress) --
        {
            const float4* src = (const float4*)(g_WhP + (size_t)(gbase + o * 2) * 4096);
#pragma unroll
            for (int p = 0; p < 8; p++) {
                int idx = t + p * 256;
                int gs = idx >> 10, rest = idx & 1023;
                int kt = rest >> 5, f4i = rest & 31;
                uint32_t daddr = whs_sb + (uint32_t)(gs * 4352 + kt * 136 + f4i * 4) * 4u;
                asm volatile("cp.async.cg.shared.global [%0], [%1], 16;"
                             :: "r"(daddr), "l"(src + idx));
            }
            asm volatile("cp.async.commit_group;");
        }

        // -- compress chunk o: 8 rows/warp, depth-2 pipelined A loads --
        {
            const int4* abase = (const int4*)(Ab + (size_t)(i0 + warp * 8) * CC + J0 + o * 128) + lane;
            int4 av = __ldcs(abase);
#pragma unroll
            for (int rr = 0; rr < 8; rr++) {
                int4 nv = av;
                if (rr < 7) nv = __ldcs(abase + (rr + 1) * (CC / 4));
                int rowl = warp * 8 + rr;
                int diagr = (i0 + rowl) - (J0 + o * 128);
                int jr = lane * 4;
                bool v0 = (av.x > 0) || (jr     == diagr);
                bool v1 = (av.y > 0) || (jr + 1 == diagr);
                bool v2 = (av.z > 0) || (jr + 2 == diagr);
                bool v3 = (av.w > 0) || (jr + 3 == diagr);
                uint32_t b0 = __ballot_sync(0xffffffffu, v0);
                uint32_t b1 = __ballot_sync(0xffffffffu, v1);
                uint32_t b2 = __ballot_sync(0xffffffffu, v2);
                uint32_t b3 = __ballot_sync(0xffffffffu, v3);
                float4 sv = *(const float4*)(s2S + o * 128 + jr);
                float m2 = -3.0e38f;
                m2 = fmaxf(m2, v0 ? sv.x : -3.0e38f);
                m2 = fmaxf(m2, v1 ? sv.y : -3.0e38f);
                m2 = fmaxf(m2, v2 ? sv.z : -3.0e38f);
                m2 = fmaxf(m2, v3 ? sv.w : -3.0e38f);
#pragma unroll
                for (int off = 16; off; off >>= 1)
                    m2 = fmaxf(m2, __shfl_xor_sync(0xffffffffu, m2, off));
                if (lane == 0) {
                    maskC[rowl][0] = b0;
                    maskC[rowl][1] = b1;
                    maskC[rowl][2] = b2;
                    maskC[rowl][3] = b3;
                    float xm = s1s[rowl] + m2;
                    xm = fmaxf(xm, 0.2f * xm);          // chunk logit max
                    float mo = msS[rowl];
                    float mn = fmaxf(mo, xm);
                    fsS[rowl] = ex2f(mo - mn);          // rescale (0 if first)
                    msS[rowl] = mn;
                }
                av = nv;
            }
        }
        asm volatile("cp.async.wait_group 0;" ::: "memory");
        __syncthreads();

        // -- rescale accumulators by this chunk's factor --
        float fA = fsS[myrowA], fB = fsS[myrowB];
        float mAv = msS[myrowA], mBv = msS[myrowB];
        float s1A = s1s[myrowA], s1B = s1s[myrowB];
        float cA  = s1A - mAv,  c5A = 0.2f * s1A - mAv;
        float cB  = s1B - mBv,  c5B = 0.2f * s1B - mBv;
#pragma unroll
        for (int nf = 0; nf < 8; nf++) {
            acc[nf].x *= fA; acc[nf].y *= fA;
            acc[nf].z *= fB; acc[nf].w *= fB;
        }
        lA *= fA; lB *= fB;

        uint32_t mwA = maskC[myrowA][tg];
        uint32_t mwB = maskC[myrowB][tg];
        const float2* s2pg = s2pair + (o * 16 + grp * 8) * 4 + tg;
        const float*  wpg  = whsP + grp * 4352 + tg * 136;

#pragma unroll
        for (int kk = 0; kk < 8; kk++) {
            float2 sp = s2pg[kk * 4];
            int bit0 = grp * 16 + kk * 2, bit1 = bit0 + 1;

            float ya0 = fmaxf(sp.x + cA, fmaf(0.2f, sp.x, c5A));
            float ya1 = fmaxf(sp.y + cA, fmaf(0.2f, sp.y, c5A));
            float yb0 = fmaxf(sp.x + cB, fmaf(0.2f, sp.x, c5B));
            float yb1 = fmaxf(sp.y + cB, fmaf(0.2f, sp.y, c5B));

            ya0 = ((mwA >> bit0) & 1u) ? ya0 : -1000.f;
            ya1 = ((mwA >> bit1) & 1u) ? ya1 : -1000.f;
            yb0 = ((mwB >> bit0) & 1u) ? yb0 : -1000.f;
            yb1 = ((mwB >> bit1) & 1u) ? yb1 : -1000.f;

            // raw fp32 p; HMMA.TF32 truncates operands to tf32 in HW
            float pa0 = ex2f(ya0);
            float pa1 = ex2f(ya1);
            float pb0 = ex2f(yb0);
            float pb1 = ex2f(yb1);
            lA += pa0 + pa1;
            lB += pb0 + pb1;

            uint32_t a0 = __float_as_uint(pa0);
            uint32_t a1 = __float_as_uint(pb0);
            uint32_t a2 = __float_as_uint(pa1);
            uint32_t a3 = __float_as_uint(pb1);

            const float* wk = wpg + kk * 4 * 136 + g * 2;
#pragma unroll
            for (int nf = 0; nf < 8; nf++) {
                float2 wp = *(const float2*)(wk + nf * 16);
                mma_tf32((float*)&acc[nf],
                         a0, a1, a2, a3,
                         __float_as_uint(wp.x), __float_as_uint(wp.y));
            }
        }
    }

    // ---- cross-group reduction (alias whsP) + partial write ----
    __syncthreads();
    if (t < 64) g_partm[bid][t] = msS[t];
    float4* accS = (float4*)whsP;
    if (grp == 1) {
#pragma unroll
        for (int nf = 0; nf < 8; nf++) accS[lt * 9 + nf] = acc[nf];
        accS[lt * 9 + 8] = make_float4(lA, lB, 0.f, 0.f);
    }
    __syncthreads();
    if (grp == 0) {
#pragma unroll
        for (int nf = 0; nf < 8; nf++) {
            float4 o = accS[lt * 9 + nf];
            acc[nf].x += o.x; acc[nf].y += o.y; acc[nf].z += o.z; acc[nf].w += o.w;
        }
        float4 lo = accS[lt * 9 + 8];
        lA += lo.x; lB += lo.y;
        lA += __shfl_xor_sync(0xffffffffu, lA, 1);
        lA += __shfl_xor_sync(0xffffffffu, lA, 2);
        lB += __shfl_xor_sync(0xffffffffu, lB, 1);
        lB += __shfl_xor_sync(0xffffffffu, lB, 2);

        int row_lo = m0 + g, row_hi = row_lo + 8;
#pragma unroll
        for (int nf = 0; nf < 8; nf++) {
            int col = nf * 8 + 2 * tg;
            *(float2*)&g_part[bid][row_lo][col] = make_float2(acc[nf].x, acc[nf].y);
            *(float2*)&g_part[bid][row_hi][col] = make_float2(acc[nf].z, acc[nf].w);
        }
        if (tg == 0) {
            g_part[bid][row_lo][64] = lA;
            g_part[bid][row_hi][64] = lB;
        }
    }

    // ---- fused combine: last-arriving half merges both and writes out ----
    __threadfence();
    __syncthreads();
    int* flag = (int*)smemraw;                 // maskC no longer needed
    if (t == 0) flag[0] = atomicAdd(&g_done[tile], 1);
    __syncthreads();
    if (flag[0] == 1) {
        __threadfence();                       // acquire partner's writes
        int p0 = tile * 2, p1 = p0 + 1;
        int ri = t >> 2, cq = t & 3;

        float mh0 = g_partm[p0][ri], mh1 = g_partm[p1][ri];
        float M = fmaxf(mh0, mh1);
        float w0 = ex2f(mh0 - M), w1 = ex2f(mh1 - M);
        float l = g_part[p0][ri][64] * w0 + g_part[p1][ri][64] * w1;
        float inv = 1.f / l;

        size_t rowbase = ((size_t)tile * 64 + ri) * FF;
#pragma unroll
        for (int q = 0; q < 4; q++) {
            int col = cq * 16 + q * 4;
            float4 x0 = *(const float4*)&g_part[p0][ri][col];
            float4 x1 = *(const float4*)&g_part[p1][ri][col];
            float4 v;
            v.x = fmaxf((x0.x * w0 + x1.x * w1) * inv, 0.f);
            v.y = fmaxf((x0.y * w0 + x1.y * w1) * inv, 0.f);
            v.z = fmaxf((x0.z * w0 + x1.z * w1) * inv, 0.f);
            v.w = fmaxf((x0.w * w0 + x1.w * w1) * inv, 0.f);
            *(float4*)(out + rowbase + col) = v;
        }
        if (t == 0) g_done[tile] = 0;          // reset for next graph replay
    }
}

// ---------------------------------------------------------------------------
extern "C" void kernel_launch(void* const* d_in, const int* in_sizes, int n_in,
                              void* d_out, int out_size)
{
    const float* H = (const float*)d_in[0];   // (8, 2048, 128) f32
    const int*   A = (const int*)d_in[1];     // (8, 2048, 2048) i32
    const float* W = (const float*)d_in[2];   // (128, 64) f32
    const float* a = (const float*)d_in[3];   // (128,) f32
    float* out = (float*)d_out;               // (8, 2048, 64) f32

    cudaFuncSetAttribute(k_out, cudaFuncAttributeMaxDynamicSharedMemorySize, KOUT_SMEM);

    k_wh<<<NROWS / 32, 256>>>(H, W, a);
    k_out<<<512, 256, KOUT_SMEM>>>(A, out);
}

// round 15
// speedup vs baseline: 1.0211x; 1.0211x over previous
#include <cuda_runtime.h>
#include <cuda_bf16.h>
#include <cstdint>

#define BB 8
#define CC 2048
#define FIN 128
#define FF 64
#define NROWS (BB*CC)
#define LOG2E 1.4426950408889634f

// Scratch (__device__ globals: allocation-free rule)
// g_WhP: 4-pack layout, per 64-row group (= global row>>6), 4096 floats:
//   [grp64*4096 + kt*128 + c*4 + e],  kt=(q>>3)*4+(q&3) for row q (pairs q,q+4),
//   c = col&31, e: 0=(q,c) 1=(q+4,c) 2=(q,c+32) 3=(q+4,c+32).  tf32-rounded.
__device__ float g_WhP[(size_t)NROWS * FF];
__device__ float g_s1[NROWS];                 // s1 * log2e
__device__ float g_s2[NROWS];                 // s2 * log2e
__device__ float g_part[512][64][72];         // per (tile,half): unnorm acc + l at col 64
__device__ float g_partm[512][64];            // per (tile,half): running row max (exp2 dom)

__device__ __forceinline__ float f2tf32f(float x) {
    uint32_t r;
    asm("cvt.rna.tf32.f32 %0, %1;" : "=r"(r) : "f"(x));
    return __uint_as_float(r);
}
__device__ __forceinline__ float ex2f(float x) {
    float r;
    asm("ex2.approx.f32 %0, %1;" : "=f"(r) : "f"(x));
    return r;
}
__device__ __forceinline__ void mma_tf32(float* c,
                                         uint32_t a0, uint32_t a1, uint32_t a2, uint32_t a3,
                                         uint32_t b0, uint32_t b1) {
    asm volatile(
        "mma.sync.aligned.m16n8k8.row.col.f32.tf32.tf32.f32 "
        "{%0,%1,%2,%3}, {%4,%5,%6,%7}, {%8,%9}, {%0,%1,%2,%3};"
        : "+f"(c[0]), "+f"(c[1]), "+f"(c[2]), "+f"(c[3])
        : "r"(a0), "r"(a1), "r"(a2), "r"(a3), "r"(b0), "r"(b1));
}

// ---------------------------------------------------------------------------
// Kernel 1: Wh = H @ W, 32 rows/block (grid 512), + s1,s2 (x log2e).
// Thread tx owns cols (tx, tx+32); rows = two (q,q+4) pairs -> the 4-pack
// g_WhP float4 writes stay in-thread.
// ---------------------------------------------------------------------------
__global__ __launch_bounds__(256) void k_wh(const float* __restrict__ H,
                                            const float* __restrict__ W,
                                            const float* __restrict__ a)
{
    __shared__ float HsT[32][46];     // [k][perm(row)], perm(r)=r+(r>>3)*4
    __shared__ float Ws[32][68];      // [k][col]

    int t  = threadIdx.x;
    int tx = t & 31;                  // cols tx, tx+32
    int ty = t >> 5;                  // 0..7
    int m  = ty >> 1;                 // 8-row block 0..3
    int s0 = (ty & 1) * 2;            // rows: m*8+s0, +1, +4, +5
    int r0 = blockIdx.x * 32;

    float acc[4][2] = {};             // [0]=q0 [1]=q0+1 [2]=q0+4 [3]=q0+5 ; [.][0]=col tx [.][1]=col tx+32

    for (int kc = 0; kc < 4; kc++) {
        __syncthreads();
        {   // H tile transposed: 32 rows x 32 k (1 float4/thread)
            int r = t >> 3, c4 = t & 7;
            float4 v = *(const float4*)(H + (size_t)(r0 + r) * FIN + kc * 32 + c4 * 4);
            int pr = r + ((r >> 3) << 2);
            HsT[c4 * 4 + 0][pr] = v.x;
            HsT[c4 * 4 + 1][pr] = v.y;
            HsT[c4 * 4 + 2][pr] = v.z;
            HsT[c4 * 4 + 3][pr] = v.w;
        }
        {   // W chunk
#pragma unroll
            for (int p = 0; p < 2; p++) {
                int idx = t + p * 256;
                int row = idx >> 4, c4 = idx & 15;
                *(float4*)&Ws[row][c4 * 4] = *(const float4*)(W + (size_t)(kc * 32 + row) * FF + c4 * 4);
            }
        }
        __syncthreads();

#pragma unroll
        for (int k = 0; k < 32; k++) {
            float w0 = Ws[k][tx];
            float w1 = Ws[k][tx + 32];
            float2 hlo = *(const float2*)&HsT[k][m * 12 + s0];       // q0, q0+1
            float2 hhi = *(const float2*)&HsT[k][m * 12 + s0 + 4];   // q0+4, q0+5
            acc[0][0] = fmaf(hlo.x, w0, acc[0][0]); acc[0][1] = fmaf(hlo.x, w1, acc[0][1]);
            acc[1][0] = fmaf(hlo.y, w0, acc[1][0]); acc[1][1] = fmaf(hlo.y, w1, acc[1][1]);
            acc[2][0] = fmaf(hhi.x, w0, acc[2][0]); acc[2][1] = fmaf(hhi.x, w1, acc[2][1]);
            acc[3][0] = fmaf(hhi.y, w0, acc[3][0]); acc[3][1] = fmaf(hhi.y, w1, acc[3][1]);
        }
    }

    // epilogue: s1/s2 per row (warp reduce over tx)
    float a10 = a[tx], a11 = a[tx + 32];
    float a20 = a[FF + tx], a21 = a[FF + tx + 32];
    int qrow[4] = { m * 8 + s0, m * 8 + s0 + 1, m * 8 + s0 + 4, m * 8 + s0 + 5 };

#pragma unroll
    for (int rr = 0; rr < 4; rr++) {
        int r = r0 + qrow[rr];
        float p1 = acc[rr][0] * a10 + acc[rr][1] * a11;
        float p2 = acc[rr][0] * a20 + acc[rr][1] * a21;
#pragma unroll
        for (int off = 16; off; off >>= 1) {
            p1 += __shfl_xor_sync(0xffffffffu, p1, off);
            p2 += __shfl_xor_sync(0xffffffffu, p2, off);
        }
        if (tx == 0) { g_s1[r] = p1 * LOG2E; g_s2[r] = p2 * LOG2E; }
    }

    // 4-pack g_WhP writes: kt = m*4+s0 (+1); float4 = (q,c),(q+4,c),(q,c+32),(q+4,c+32)
    float* dst = g_WhP + (size_t)(blockIdx.x >> 1) * 4096
               + (size_t)((blockIdx.x & 1) * 16) * 128;
    {
        int kt = m * 4 + s0;
        float4 v0, v1;
        v0.x = f2tf32f(acc[0][0]); v0.y = f2tf32f(acc[2][0]);
        v0.z = f2tf32f(acc[0][1]); v0.w = f2tf32f(acc[2][1]);
        v1.x = f2tf32f(acc[1][0]); v1.y = f2tf32f(acc[3][0]);
        v1.z = f2tf32f(acc[1][1]); v1.w = f2tf32f(acc[3][1]);
        *(float4*)(dst + kt * 128 + tx * 4)       = v0;
        *(float4*)(dst + (kt + 1) * 128 + tx * 4) = v1;
    }
}

// ---------------------------------------------------------------------------
// k_out: SINGLE-PASS online-softmax @ Wh (R12 structure). Grid 512, 4/SM.
// B-fragments via LDS.128 (4-pack layout): one load feeds two MMAs.
// ---------------------------------------------------------------------------
// dynamic smem (bytes):
//   maskC : uint32[64][8]       @ 0      (2048)
//   s2S   : float [1024]        @ 2048   (4096)
//   s2pair: float2[512]         @ 6144   (4096)
//   whsP  : float [2][4352]     @ 10240  (34816)  (aliased as accS at end)
//   s1s   : float [64]          @ 45056  (256)
//   msS   : float [64]          @ 45312  (256)
//   fsS   : float [64]          @ 45568  (256)
#define KOUT_SMEM 45824

__global__ __launch_bounds__(256, 4) void k_out(const int* __restrict__ A)
{
    extern __shared__ char smemraw[];
    uint32_t (*maskC)[8] = (uint32_t(*)[8])smemraw;
    float*  s2S    = (float*)(smemraw + 2048);
    float2* s2pair = (float2*)(smemraw + 6144);
    float*  whsP   = (float*)(smemraw + 10240);
    float*  s1s    = (float*)(smemraw + 45056);
    float*  msS    = (float*)(smemraw + 45312);
    float*  fsS    = (float*)(smemraw + 45568);

    int t = threadIdx.x;
    int lane = t & 31;
    int warp = t >> 5;
    int grp  = t >> 7;
    int lt   = t & 127;
    int wg   = warp & 3;
    int g = lane >> 2, tg = lane & 3;
    int m0 = wg * 16;

    int bid  = blockIdx.x;
    int half = bid & 1;
    int tile = bid >> 1;
    int b  = tile >> 5;
    int i0 = (tile & 31) << 6;
    int J0 = half << 10;
    const int* Ab = A + (size_t)b * CC * CC;

    if (t < 64) {
        s1s[t] = g_s1[b * CC + i0 + t];
        msS[t] = -3.0e38f;
    }
    for (int q = t; q < 1024; q += 256) s2S[q] = g_s2[b * CC + J0 + q];
    __syncthreads();
#pragma unroll
    for (int p = 0; p < 2; p++) {
        int idx = t + p * 256;
        int gj = idx >> 2, tgq = idx & 3;
        s2pair[idx] = make_float2(s2S[gj * 8 + tgq], s2S[gj * 8 + tgq + 4]);
    }

    float4 acc[8];
#pragma unroll
    for (int nf = 0; nf < 8; nf++) acc[nf] = make_float4(0.f, 0.f, 0.f, 0.f);
    float lA = 0.f, lB = 0.f;

    int gbase = (b * 32) + (J0 >> 6);
    int myrowA = m0 + g, myrowB = m0 + g + 8;

    uint32_t whs_sb = (uint32_t)__cvta_generic_to_shared(whsP);

    for (int o = 0; o < 8; o++) {
        __syncthreads();                     // protect maskC/whsP/fsS reuse

        // -- stage Wh tile o via cp.async (drains during compress) --
        {
            const float4* src = (const float4*)(g_WhP + (size_t)(gbase + o * 2) * 4096);
#pragma unroll
            for (int p = 0; p < 8; p++) {
                int idx = t + p * 256;
                int gs = idx >> 10, rest = idx & 1023;
                int kt = rest >> 5, f4i = rest & 31;
                uint32_t daddr = whs_sb + (uint32_t)(gs * 4352 + kt * 136 + f4i * 4) * 4u;
                asm volatile("cp.async.cg.shared.global [%0], [%1], 16;"
                             :: "r"(daddr), "l"(src + idx));
            }
            asm volatile("cp.async.commit_group;");
        }

        // -- compress chunk o: 8 rows/warp, depth-2 pipelined A loads --
        {
            const int4* abase = (const int4*)(Ab + (size_t)(i0 + warp * 8) * CC + J0 + o * 128) + lane;
            int4 av = __ldcs(abase);
#pragma unroll
            for (int rr = 0; rr < 8; rr++) {
                int4 nv = av;
                if (rr < 7) nv = __ldcs(abase + (rr + 1) * (CC / 4));
                int rowl = warp * 8 + rr;
                int diagr = (i0 + rowl) - (J0 + o * 128);
                int jr = lane * 4;
                bool v0 = (av.x > 0) || (jr     == diagr);
                bool v1 = (av.y > 0) || (jr + 1 == diagr);
                bool v2 = (av.z > 0) || (jr + 2 == diagr);
                bool v3 = (av.w > 0) || (jr + 3 == diagr);
                uint32_t b0 = __ballot_sync(0xffffffffu, v0);
                uint32_t b1 = __ballot_sync(0xffffffffu, v1);
                uint32_t b2 = __ballot_sync(0xffffffffu, v2);
                uint32_t b3 = __ballot_sync(0xffffffffu, v3);
                float4 sv = *(const float4*)(s2S + o * 128 + jr);
                float m2 = -3.0e38f;
                m2 = fmaxf(m2, v0 ? sv.x : -3.0e38f);
                m2 = fmaxf(m2, v1 ? sv.y : -3.0e38f);
                m2 = fmaxf(m2, v2 ? sv.z : -3.0e38f);
                m2 = fmaxf(m2, v3 ? sv.w : -3.0e38f);
#pragma unroll
                for (int off = 16; off; off >>= 1)
                    m2 = fmaxf(m2, __shfl_xor_sync(0xffffffffu, m2, off));
                if (lane == 0) {
                    maskC[rowl][0] = b0;
                    maskC[rowl][1] = b1;
                    maskC[rowl][2] = b2;
                    maskC[rowl][3] = b3;
                    float xm = s1s[rowl] + m2;
                    xm = fmaxf(xm, 0.2f * xm);          // chunk logit max
                    float mo = msS[rowl];
                    float mn = fmaxf(mo, xm);
                    fsS[rowl] = ex2f(mo - mn);          // rescale (0 if first)
                    msS[rowl] = mn;
                }
                av = nv;
            }
        }
        asm volatile("cp.async.wait_group 0;" ::: "memory");
        __syncthreads();

        // -- rescale accumulators by this chunk's factor --
        float fA = fsS[myrowA], fB = fsS[myrowB];
        float mAv = msS[myrowA], mBv = msS[myrowB];
        float s1A = s1s[myrowA], s1B = s1s[myrowB];
        float cA  = s1A - mAv,  c5A = 0.2f * s1A - mAv;
        float cB  = s1B - mBv,  c5B = 0.2f * s1B - mBv;
#pragma unroll
        for (int nf = 0; nf < 8; nf++) {
            acc[nf].x *= fA; acc[nf].y *= fA;
            acc[nf].z *= fB; acc[nf].w *= fB;
        }
        lA *= fA; lB *= fB;

        uint32_t mwA = maskC[myrowA][tg];
        uint32_t mwB = maskC[myrowB][tg];
        const float2* s2pg = s2pair + (o * 16 + grp * 8) * 4 + tg;
        const float*  wpg  = whsP + grp * 4352 + tg * 136 + g * 4;

#pragma unroll
        for (int kk = 0; kk < 8; kk++) {
            float2 sp = s2pg[kk * 4];
            int bit0 = grp * 16 + kk * 2, bit1 = bit0 + 1;

            float ya0 = fmaxf(sp.x + cA, fmaf(0.2f, sp.x, c5A));
            float ya1 = fmaxf(sp.y + cA, fmaf(0.2f, sp.y, c5A));
            float yb0 = fmaxf(sp.x + cB, fmaf(0.2f, sp.x, c5B));
            float yb1 = fmaxf(sp.y + cB, fmaf(0.2f, sp.y, c5B));

            ya0 = ((mwA >> bit0) & 1u) ? ya0 : -1000.f;
            ya1 = ((mwA >> bit1) & 1u) ? ya1 : -1000.f;
            yb0 = ((mwB >> bit0) & 1u) ? yb0 : -1000.f;
            yb1 = ((mwB >> bit1) & 1u) ? yb1 : -1000.f;

            // raw fp32 p; HMMA.TF32 truncates operands to tf32 in HW
            float pa0 = ex2f(ya0);
            float pa1 = ex2f(ya1);
            float pb0 = ex2f(yb0);
            float pb1 = ex2f(yb1);
            lA += pa0 + pa1;
            lB += pb0 + pb1;

            uint32_t a0 = __float_as_uint(pa0);
            uint32_t a1 = __float_as_uint(pb0);
            uint32_t a2 = __float_as_uint(pa1);
            uint32_t a3 = __float_as_uint(pb1);

            const float* wk = wpg + kk * 4 * 136;
#pragma unroll
            for (int nf = 0; nf < 4; nf++) {
                float4 wp = *(const float4*)(wk + nf * 32);   // (jl0,c)(jl1,c)(jl0,c+32)(jl1,c+32)
                mma_tf32((float*)&acc[nf],
                         a0, a1, a2, a3,
                         __float_as_uint(wp.x), __float_as_uint(wp.y));
                mma_tf32((float*)&acc[nf + 4],
                         a0, a1, a2, a3,
                         __float_as_uint(wp.z), __float_as_uint(wp.w));
            }
        }
    }

    // ---- cross-group reduction (alias whsP) + partial write ----
    __syncthreads();
    if (t < 64) g_partm[bid][t] = msS[t];
    float4* accS = (float4*)whsP;
    if (grp == 1) {
#pragma unroll
        for (int nf = 0; nf < 8; nf++) accS[lt * 9 + nf] = acc[nf];
        accS[lt * 9 + 8] = make_float4(lA, lB, 0.f, 0.f);
    }
    __syncthreads();
    if (grp == 0) {
#pragma unroll
        for (int nf = 0; nf < 8; nf++) {
            float4 o = accS[lt * 9 + nf];
            acc[nf].x += o.x; acc[nf].y += o.y; acc[nf].z += o.z; acc[nf].w += o.w;
        }
        float4 lo = accS[lt * 9 + 8];
        lA += lo.x; lB += lo.y;
        lA += __shfl_xor_sync(0xffffffffu, lA, 1);
        lA += __shfl_xor_sync(0xffffffffu, lA, 2);
        lB += __shfl_xor_sync(0xffffffffu, lB, 1);
        lB += __shfl_xor_sync(0xffffffffu, lB, 2);

        int row_lo = m0 + g, row_hi = row_lo + 8;
        // NOTE acc col mapping: nf<4 -> cols nf*8.., nf>=4 -> cols 32+(nf-4)*8..
#pragma unroll
        for (int nf = 0; nf < 8; nf++) {
            int col = (nf < 4) ? (nf * 8 + 2 * tg) : (32 + (nf - 4) * 8 + 2 * tg);
            *(float2*)&g_part[bid][row_lo][col] = make_float2(acc[nf].x, acc[nf].y);
            *(float2*)&g_part[bid][row_hi][col] = make_float2(acc[nf].z, acc[nf].w);
        }
        if (tg == 0) {
            g_part[bid][row_lo][64] = lA;
            g_part[bid][row_hi][64] = lB;
        }
    }
}

// ---------------------------------------------------------------------------
// k_comb: weighted combine of halves: out = relu((Σ acc_h w_h)/(Σ l_h w_h)),
// w_h = exp2(m_h - max(m)).
// ---------------------------------------------------------------------------
__global__ __launch_bounds__(256) void k_comb(float* __restrict__ out)
{
    int tile = blockIdx.x;
    int t = threadIdx.x;
    int ri = t >> 2, cq = t & 3;
    int p0 = tile * 2, p1 = p0 + 1;

    float m0 = g_partm[p0][ri], m1 = g_partm[p1][ri];
    float M = fmaxf(m0, m1);
    float w0 = ex2f(m0 - M), w1 = ex2f(m1 - M);
    float l = g_part[p0][ri][64] * w0 + g_part[p1][ri][64] * w1;
    float inv = 1.f / l;

    size_t rowbase = ((size_t)tile * 64 + ri) * FF;
#pragma unroll
    for (int q = 0; q < 4; q++) {
        int col = cq * 16 + q * 4;
        float4 a0 = *(const float4*)&g_part[p0][ri][col];
        float4 a1 = *(const float4*)&g_part[p1][ri][col];
        float4 v;
        v.x = fmaxf((a0.x * w0 + a1.x * w1) * inv, 0.f);
        v.y = fmaxf((a0.y * w0 + a1.y * w1) * inv, 0.f);
        v.z = fmaxf((a0.z * w0 + a1.z * w1) * inv, 0.f);
        v.w = fmaxf((a0.w * w0 + a1.w * w1) * inv, 0.f);
        *(float4*)(out + rowbase + col) = v;
    }
}

// ---------------------------------------------------------------------------
extern "C" void kernel_launch(void* const* d_in, const int* in_sizes, int n_in,
                              void* d_out, int out_size)
{
    const float* H = (const float*)d_in[0];   // (8, 2048, 128) f32
    const int*   A = (const int*)d_in[1];     // (8, 2048, 2048) i32
    const float* W = (const float*)d_in[2];   // (128, 64) f32
    const float* a = (const float*)d_in[3];   // (128,) f32
    float* out = (float*)d_out;               // (8, 2048, 64) f32

    cudaFuncSetAttribute(k_out, cudaFuncAttributeMaxDynamicSharedMemorySize, KOUT_SMEM);

    k_wh<<<NROWS / 32, 256>>>(H, W, a);
    k_out<<<512, 256, KOUT_SMEM>>>(A);
    k_comb<<<256, 256>>>(out);
}

// round 16
// speedup vs baseline: 1.0489x; 1.0272x over previous
#include <cuda_runtime.h>
#include <cuda_bf16.h>
#include <cstdint>

#define BB 8
#define CC 2048
#define FIN 128
#define FF 64
#define NROWS (BB*CC)
#define LOG2E 1.4426950408889634f

// Scratch (__device__ globals: allocation-free rule)
// g_WhP: 4-pack layout, per 64-row group (= global row>>6), 4096 floats:
//   [grp64*4096 + kt*128 + c*4 + e],  kt=(q>>3)*4+(q&3) for row q (pairs q,q+4),
//   c = col&31, e: 0=(q,c) 1=(q+4,c) 2=(q,c+32) 3=(q+4,c+32).  tf32-rounded.
__device__ float g_WhP[(size_t)NROWS * FF];
__device__ float g_s1[NROWS];                 // s1 * log2e
__device__ float g_s2[NROWS];                 // s2 * log2e
__device__ float g_part[512][64][72];         // per (tile,half): unnorm acc + l at col 64
__device__ float g_partm[512][64];            // per (tile,half): running row max (exp2 dom)

__device__ __forceinline__ float f2tf32f(float x) {
    uint32_t r;
    asm("cvt.rna.tf32.f32 %0, %1;" : "=r"(r) : "f"(x));
    return __uint_as_float(r);
}
__device__ __forceinline__ float ex2f(float x) {
    float r;
    asm("ex2.approx.f32 %0, %1;" : "=f"(r) : "f"(x));
    return r;
}
__device__ __forceinline__ void mma_tf32(float* c,
                                         uint32_t a0, uint32_t a1, uint32_t a2, uint32_t a3,
                                         uint32_t b0, uint32_t b1) {
    asm volatile(
        "mma.sync.aligned.m16n8k8.row.col.f32.tf32.tf32.f32 "
        "{%0,%1,%2,%3}, {%4,%5,%6,%7}, {%8,%9}, {%0,%1,%2,%3};"
        : "+f"(c[0]), "+f"(c[1]), "+f"(c[2]), "+f"(c[3])
        : "r"(a0), "r"(a1), "r"(a2), "r"(a3), "r"(b0), "r"(b1));
}

// ---------------------------------------------------------------------------
// Kernel 1 (tensor-core version): Wh = H @ W via tf32 MMA; s1,s2 in FULL fp32
// via the associativity trick s = H · (W·a)  (raw H, raw W — accuracy-critical).
// 64 rows/block, 128 threads (4 warps x m16), grid 256.
// smem (floats): Wp[8192] | Hs[64][132] (aliased as WhS[64][68]) | aS[128] | waS[128]x2
// ---------------------------------------------------------------------------
#define KWH_SMEM 68096

__global__ __launch_bounds__(128) void k_wh(const float* __restrict__ H,
                                            const float* __restrict__ W,
                                            const float* __restrict__ a)
{
    extern __shared__ float sm[];
    float*  Wp  = sm;                         // 8192 floats (4-pack of tf32 W)
    float*  Hs  = sm + 8192;                  // 64 x 132 raw fp32 H
    float*  WhS = sm + 8192;                  // alias (64 x 68), used after MMA
    float*  aS  = sm + 8192 + 8448;           // 128
    float2* waS = (float2*)(sm + 8192 + 8448 + 128);  // 128 x {wa1,wa2}*log2e

    int t = threadIdx.x;
    int lane = t & 31, warp = t >> 5;
    int g = lane >> 2, tg = lane & 3;
    int W0 = warp * 16;
    int r0 = blockIdx.x * 64;

    // phase 1: a -> smem, H tile -> smem (raw fp32; MMA HW truncates to tf32)
    aS[t] = a[t];
    {
        const float4* src = (const float4*)(H + (size_t)r0 * FIN);
#pragma unroll
        for (int p = 0; p < 16; p++) {
            int idx = t + p * 128;
            int r = idx >> 5, c4 = idx & 31;
            *(float4*)&Hs[r * 132 + c4 * 4] = src[idx];
        }
    }
    __syncthreads();

    // phase 2: W row k=t -> Wp (tf32 RNA, 4-pack) + wa1/wa2 from RAW W
    {
        int k = t;
        const float4* wrow = (const float4*)(W + k * FF);
        float wa1 = 0.f, wa2 = 0.f;
        int ktb = (k >> 3) * 512 + (k & 3) * 128;
        int e0  = (k >> 2) & 1;
#pragma unroll
        for (int i = 0; i < 16; i++) {
            int c4 = (i + (k & 15)) & 15;            // stagger: avoid STS bank pileup
            float4 wv = wrow[c4];
#pragma unroll
            for (int j = 0; j < 4; j++) {
                int c = c4 * 4 + j;
                float w = (j == 0) ? wv.x : (j == 1) ? wv.y : (j == 2) ? wv.z : wv.w;
                wa1 = fmaf(w, aS[c], wa1);
                wa2 = fmaf(w, aS[64 + c], wa2);
                Wp[ktb + (c & 31) * 4 + e0 + 2 * (c >> 5)] = f2tf32f(w);
            }
        }
        waS[k] = make_float2(wa1 * LOG2E, wa2 * LOG2E);
    }
    __syncthreads();

    // phase 3a: s1/s2 in fp32 (thread pair per row; k split in halves)
    {
        int r = t >> 1, half = t & 1;
        const float*  hrow = &Hs[r * 132 + half * 64];
        const float2* wv   = waS + half * 64;
        float p1 = 0.f, p2 = 0.f;
#pragma unroll
        for (int k = 0; k < 64; k++) {
            float h = hrow[k];
            float2 w2 = wv[k];
            p1 = fmaf(h, w2.x, p1);
            p2 = fmaf(h, w2.y, p2);
        }
        p1 += __shfl_xor_sync(0xffffffffu, p1, 1);
        p2 += __shfl_xor_sync(0xffffffffu, p2, 1);
        if (half == 0) { g_s1[r0 + r] = p1; g_s2[r0 + r] = p2; }
    }

    // phase 3b: MMA mainloop (16 k-steps x 8 n-frags)
    float4 acc[8];
#pragma unroll
    for (int nf = 0; nf < 8; nf++) acc[nf] = make_float4(0.f, 0.f, 0.f, 0.f);

#pragma unroll
    for (int s = 0; s < 16; s++) {
        int k0 = s * 8;
        uint32_t a0 = __float_as_uint(Hs[(W0 + g) * 132 + k0 + tg]);
        uint32_t a1 = __float_as_uint(Hs[(W0 + g + 8) * 132 + k0 + tg]);
        uint32_t a2 = __float_as_uint(Hs[(W0 + g) * 132 + k0 + tg + 4]);
        uint32_t a3 = __float_as_uint(Hs[(W0 + g + 8) * 132 + k0 + tg + 4]);
        const float* wk = Wp + s * 512 + tg * 128 + g * 4;
#pragma unroll
        for (int nf = 0; nf < 4; nf++) {
            float4 wp = *(const float4*)(wk + nf * 32);
            mma_tf32((float*)&acc[nf],     a0, a1, a2, a3,
                     __float_as_uint(wp.x), __float_as_uint(wp.y));
            mma_tf32((float*)&acc[nf + 4], a0, a1, a2, a3,
                     __float_as_uint(wp.z), __float_as_uint(wp.w));
        }
    }
    __syncthreads();                     // Hs no longer needed -> reuse as WhS

    // phase 4: acc fragments -> WhS[64][68]
    {
        int rA = W0 + g;
#pragma unroll
        for (int nf = 0; nf < 8; nf++) {
            int col = (nf < 4) ? (nf * 8 + 2 * tg) : (32 + (nf - 4) * 8 + 2 * tg);
            *(float2*)&WhS[rA * 68 + col]       = make_float2(acc[nf].x, acc[nf].y);
            *(float2*)&WhS[(rA + 8) * 68 + col] = make_float2(acc[nf].z, acc[nf].w);
        }
    }
    __syncthreads();

    // phase 5: WhS -> g_WhP 4-pack, tf32 RNA rounded
    {
        float* dst = g_WhP + (size_t)blockIdx.x * 4096;
#pragma unroll
        for (int p = 0; p < 8; p++) {
            int f = t + p * 128;
            int kt = f >> 5, cl = f & 31;
            int q = ((kt >> 2) << 3) + (kt & 3);
            float4 v;
            v.x = f2tf32f(WhS[q * 68 + cl]);
            v.y = f2tf32f(WhS[(q + 4) * 68 + cl]);
            v.z = f2tf32f(WhS[q * 68 + cl + 32]);
            v.w = f2tf32f(WhS[(q + 4) * 68 + cl + 32]);
            *(float4*)(dst + f * 4) = v;
        }
    }
}

// ---------------------------------------------------------------------------
// k_out: SINGLE-PASS online-softmax @ Wh (R15 verbatim). Grid 512, 4/SM.
// ---------------------------------------------------------------------------
// dynamic smem (bytes):
//   maskC : uint32[64][8]       @ 0      (2048)
//   s2S   : float [1024]        @ 2048   (4096)
//   s2pair: float2[512]         @ 6144   (4096)
//   whsP  : float [2][4352]     @ 10240  (34816)  (aliased as accS at end)
//   s1s   : float [64]          @ 45056  (256)
//   msS   : float [64]          @ 45312  (256)
//   fsS   : float [64]          @ 45568  (256)
#define KOUT_SMEM 45824

__global__ __launch_bounds__(256, 4) void k_out(const int* __restrict__ A)
{
    extern __shared__ char smemraw[];
    uint32_t (*maskC)[8] = (uint32_t(*)[8])smemraw;
    float*  s2S    = (float*)(smemraw + 2048);
    float2* s2pair = (float2*)(smemraw + 6144);
    float*  whsP   = (float*)(smemraw + 10240);
    float*  s1s    = (float*)(smemraw + 45056);
    float*  msS    = (float*)(smemraw + 45312);
    float*  fsS    = (float*)(smemraw + 45568);

    int t = threadIdx.x;
    int lane = t & 31;
    int warp = t >> 5;
    int grp  = t >> 7;
    int lt   = t & 127;
    int wg   = warp & 3;
    int g = lane >> 2, tg = lane & 3;
    int m0 = wg * 16;

    int bid  = blockIdx.x;
    int half = bid & 1;
    int tile = bid >> 1;
    int b  = tile >> 5;
    int i0 = (tile & 31) << 6;
    int J0 = half << 10;
    const int* Ab = A + (size_t)b * CC * CC;

    if (t < 64) {
        s1s[t] = g_s1[b * CC + i0 + t];
        msS[t] = -3.0e38f;
    }
    for (int q = t; q < 1024; q += 256) s2S[q] = g_s2[b * CC + J0 + q];
    __syncthreads();
#pragma unroll
    for (int p = 0; p < 2; p++) {
        int idx = t + p * 256;
        int gj = idx >> 2, tgq = idx & 3;
        s2pair[idx] = make_float2(s2S[gj * 8 + tgq], s2S[gj * 8 + tgq + 4]);
    }

    float4 acc[8];
#pragma unroll
    for (int nf = 0; nf < 8; nf++) acc[nf] = make_float4(0.f, 0.f, 0.f, 0.f);
    float lA = 0.f, lB = 0.f;

    int gbase = (b * 32) + (J0 >> 6);
    int myrowA = m0 + g, myrowB = m0 + g + 8;

    uint32_t whs_sb = (uint32_t)__cvta_generic_to_shared(whsP);

    for (int o = 0; o < 8; o++) {
        __syncthreads();                     // protect maskC/whsP/fsS reuse

        // -- stage Wh tile o via cp.async (drains during compress) --
        {
            const float4* src = (const float4*)(g_WhP + (size_t)(gbase + o * 2) * 4096);
#pragma unroll
            for (int p = 0; p < 8; p++) {
                int idx = t + p * 256;
                int gs = idx >> 10, rest = idx & 1023;
                int kt = rest >> 5, f4i = rest & 31;
                uint32_t daddr = whs_sb + (uint32_t)(gs * 4352 + kt * 136 + f4i * 4) * 4u;
                asm volatile("cp.async.cg.shared.global [%0], [%1], 16;"
                             :: "r"(daddr), "l"(src + idx));
            }
            asm volatile("cp.async.commit_group;");
        }

        // -- compress chunk o: 8 rows/warp, depth-2 pipelined A loads --
        {
            const int4* abase = (const int4*)(Ab + (size_t)(i0 + warp * 8) * CC + J0 + o * 128) + lane;
            int4 av = __ldcs(abase);
#pragma unroll
            for (int rr = 0; rr < 8; rr++) {
                int4 nv = av;
                if (rr < 7) nv = __ldcs(abase + (rr + 1) * (CC / 4));
                int rowl = warp * 8 + rr;
                int diagr = (i0 + rowl) - (J0 + o * 128);
                int jr = lane * 4;
                bool v0 = (av.x > 0) || (jr     == diagr);
                bool v1 = (av.y > 0) || (jr + 1 == diagr);
                bool v2 = (av.z > 0) || (jr + 2 == diagr);
                bool v3 = (av.w > 0) || (jr + 3 == diagr);
                uint32_t b0 = __ballot_sync(0xffffffffu, v0);
                uint32_t b1 = __ballot_sync(0xffffffffu, v1);
                uint32_t b2 = __ballot_sync(0xffffffffu, v2);
                uint32_t b3 = __ballot_sync(0xffffffffu, v3);
                float4 sv = *(const float4*)(s2S + o * 128 + jr);
                float m2 = -3.0e38f;
                m2 = fmaxf(m2, v0 ? sv.x : -3.0e38f);
                m2 = fmaxf(m2, v1 ? sv.y : -3.0e38f);
                m2 = fmaxf(m2, v2 ? sv.z : -3.0e38f);
                m2 = fmaxf(m2, v3 ? sv.w : -3.0e38f);
#pragma unroll
                for (int off = 16; off; off >>= 1)
                    m2 = fmaxf(m2, __shfl_xor_sync(0xffffffffu, m2, off));
                if (lane == 0) {
                    maskC[rowl][0] = b0;
                    maskC[rowl][1] = b1;
                    maskC[rowl][2] = b2;
                    maskC[rowl][3] = b3;
                    float xm = s1s[rowl] + m2;
                    xm = fmaxf(xm, 0.2f * xm);          // chunk logit max
                    float mo = msS[rowl];
                    float mn = fmaxf(mo, xm);
                    fsS[rowl] = ex2f(mo - mn);          // rescale (0 if first)
                    msS[rowl] = mn;
                }
                av = nv;
            }
        }
        asm volatile("cp.async.wait_group 0;" ::: "memory");
        __syncthreads();

        // -- rescale accumulators by this chunk's factor --
        float fA = fsS[myrowA], fB = fsS[myrowB];
        float mAv = msS[myrowA], mBv = msS[myrowB];
        float s1A = s1s[myrowA], s1B = s1s[myrowB];
        float cA  = s1A - mAv,  c5A = 0.2f * s1A - mAv;
        float cB  = s1B - mBv,  c5B = 0.2f * s1B - mBv;
#pragma unroll
        for (int nf = 0; nf < 8; nf++) {
            acc[nf].x *= fA; acc[nf].y *= fA;
            acc[nf].z *= fB; acc[nf].w *= fB;
        }
        lA *= fA; lB *= fB;

        uint32_t mwA = maskC[myrowA][tg];
        uint32_t mwB = maskC[myrowB][tg];
        const float2* s2pg = s2pair + (o * 16 + grp * 8) * 4 + tg;
        const float*  wpg  = whsP + grp * 4352 + tg * 136 + g * 4;

#pragma unroll
        for (int kk = 0; kk < 8; kk++) {
            float2 sp = s2pg[kk * 4];
            int bit0 = grp * 16 + kk * 2, bit1 = bit0 + 1;

            float ya0 = fmaxf(sp.x + cA, fmaf(0.2f, sp.x, c5A));
            float ya1 = fmaxf(sp.y + cA, fmaf(0.2f, sp.y, c5A));
            float yb0 = fmaxf(sp.x + cB, fmaf(0.2f, sp.x, c5B));
            float yb1 = fmaxf(sp.y + cB, fmaf(0.2f, sp.y, c5B));

            ya0 = ((mwA >> bit0) & 1u) ? ya0 : -1000.f;
            ya1 = ((mwA >> bit1) & 1u) ? ya1 : -1000.f;
            yb0 = ((mwB >> bit0) & 1u) ? yb0 : -1000.f;
            yb1 = ((mwB >> bit1) & 1u) ? yb1 : -1000.f;

            // raw fp32 p; HMMA.TF32 truncates operands to tf32 in HW
            float pa0 = ex2f(ya0);
            float pa1 = ex2f(ya1);
            float pb0 = ex2f(yb0);
            float pb1 = ex2f(yb1);
            lA += pa0 + pa1;
            lB += pb0 + pb1;

            uint32_t a0 = __float_as_uint(pa0);
            uint32_t a1 = __float_as_uint(pb0);
            uint32_t a2 = __float_as_uint(pa1);
            uint32_t a3 = __float_as_uint(pb1);

            const float* wk = wpg + kk * 4 * 136;
#pragma unroll
            for (int nf = 0; nf < 4; nf++) {
                float4 wp = *(const float4*)(wk + nf * 32);
                mma_tf32((float*)&acc[nf],
                         a0, a1, a2, a3,
                         __float_as_uint(wp.x), __float_as_uint(wp.y));
                mma_tf32((float*)&acc[nf + 4],
                         a0, a1, a2, a3,
                         __float_as_uint(wp.z), __float_as_uint(wp.w));
            }
        }
    }

    // ---- cross-group reduction (alias whsP) + partial write ----
    __syncthreads();
    if (t < 64) g_partm[bid][t] = msS[t];
    float4* accS = (float4*)whsP;
    if (grp == 1) {
#pragma unroll
        for (int nf = 0; nf < 8; nf++) accS[lt * 9 + nf] = acc[nf];
        accS[lt * 9 + 8] = make_float4(lA, lB, 0.f, 0.f);
    }
    __syncthreads();
    if (grp == 0) {
#pragma unroll
        for (int nf = 0; nf < 8; nf++) {
            float4 o = accS[lt * 9 + nf];
            acc[nf].x += o.x; acc[nf].y += o.y; acc[nf].z += o.z; acc[nf].w += o.w;
        }
        float4 lo = accS[lt * 9 + 8];
        lA += lo.x; lB += lo.y;
        lA += __shfl_xor_sync(0xffffffffu, lA, 1);
        lA += __shfl_xor_sync(0xffffffffu, lA, 2);
        lB += __shfl_xor_sync(0xffffffffu, lB, 1);
        lB += __shfl_xor_sync(0xffffffffu, lB, 2);

        int row_lo = m0 + g, row_hi = row_lo + 8;
#pragma unroll
        for (int nf = 0; nf < 8; nf++) {
            int col = (nf < 4) ? (nf * 8 + 2 * tg) : (32 + (nf - 4) * 8 + 2 * tg);
            *(float2*)&g_part[bid][row_lo][col] = make_float2(acc[nf].x, acc[nf].y);
            *(float2*)&g_part[bid][row_hi][col] = make_float2(acc[nf].z, acc[nf].w);
        }
        if (tg == 0) {
            g_part[bid][row_lo][64] = lA;
            g_part[bid][row_hi][64] = lB;
        }
    }
}

// ---------------------------------------------------------------------------
// k_comb v2: 512 blocks x 128 threads (half tile each); all loads up front.
// out = relu((Σ acc_h w_h)/(Σ l_h w_h)),  w_h = exp2(m_h - max(m)).
// ---------------------------------------------------------------------------
__global__ __launch_bounds__(128) void k_comb(float* __restrict__ out)
{
    int bid = blockIdx.x;
    int tile = bid >> 1;
    int t = threadIdx.x;
    int ri = (bid & 1) * 32 + (t >> 2);
    int cq = t & 3;
    int p0 = tile * 2, p1 = p0 + 1;

    // issue all independent loads first (MLP)
    float4 x0[4], x1[4];
#pragma unroll
    for (int q = 0; q < 4; q++) {
        int col = cq * 16 + q * 4;
        x0[q] = *(const float4*)&g_part[p0][ri][col];
        x1[q] = *(const float4*)&g_part[p1][ri][col];
    }
    float mh0 = g_partm[p0][ri], mh1 = g_partm[p1][ri];
    float l0 = g_part[p0][ri][64], l1 = g_part[p1][ri][64];

    float M = fmaxf(mh0, mh1);
    float w0 = ex2f(mh0 - M), w1 = ex2f(mh1 - M);
    float inv = 1.f / (l0 * w0 + l1 * w1);

    size_t rowbase = ((size_t)tile * 64 + ri) * FF;
#pragma unroll
    for (int q = 0; q < 4; q++) {
        int col = cq * 16 + q * 4;
        float4 v;
        v.x = fmaxf((x0[q].x * w0 + x1[q].x * w1) * inv, 0.f);
        v.y = fmaxf((x0[q].y * w0 + x1[q].y * w1) * inv, 0.f);
        v.z = fmaxf((x0[q].z * w0 + x1[q].z * w1) * inv, 0.f);
        v.w = fmaxf((x0[q].w * w0 + x1[q].w * w1) * inv, 0.f);
        *(float4*)(out + rowbase + col) = v;
    }
}

// ---------------------------------------------------------------------------
extern "C" void kernel_launch(void* const* d_in, const int* in_sizes, int n_in,
                              void* d_out, int out_size)
{
    const float* H = (const float*)d_in[0];   // (8, 2048, 128) f32
    const int*   A = (const int*)d_in[1];     // (8, 2048, 2048) i32
    const float* W = (const float*)d_in[2];   // (128, 64) f32
    const float* a = (const float*)d_in[3];   // (128,) f32
    float* out = (float*)d_out;               // (8, 2048, 64) f32

    cudaFuncSetAttribute(k_wh,  cudaFuncAttributeMaxDynamicSharedMemorySize, KWH_SMEM);
    cudaFuncSetAttribute(k_out, cudaFuncAttributeMaxDynamicSharedMemorySize, KOUT_SMEM);

    k_wh<<<NROWS / 64, 128, KWH_SMEM>>>(H, W, a);
    k_out<<<512, 256, KOUT_SMEM>>>(A);
    k_comb<<<512, 128>>>(out);
}